// round 5
// baseline (speedup 1.0000x reference)
#include <cuda_runtime.h>
#include <cuda_fp16.h>
#include <cstdint>
#include <cstddef>

#define Bq 64
#define Sq 1024
#define Dq 512
#define Hq 1024
#define NBLK 128
#define BSH ((size_t)Bq * Sq * Hq)

// ---------------- persistent device state (no runtime allocation) ----------------
__device__ __half g_x16[(size_t)Bq * Sq * Dq];       // x in fp16, [B][S][D]
__device__ __half g_pack0[(size_t)4096 * 1536];      // layer0 fragment-packed weights
__device__ __half g_pack1[(size_t)4096 * 2048];      // layer1 fragment-packed weights
__device__ __half g_h0[2][Bq * Hq];                  // h0, batch-major [b][h], parity buffered
__device__ __half g_h1[2][Bq * Hq];                  // h1
__device__ float  g_c0[Bq * Hq];                     // c0, [b][h]
__device__ float  g_c1[Bq * Hq];                     // c1, [b][h]
__device__ unsigned g_bar_count;
__device__ volatile unsigned g_bar_gen;

// ---------------- merged prep (one launch -> ncu -s 5 hits lstm_main) ----------------
__device__ __forceinline__ void pack_body(const float* __restrict__ Wa,
                                          const float* __restrict__ Wb,
                                          int Ka, int Kb, int NK, __half* outp,
                                          int tid, int nth) {
    // half2 index u = ((t_id*NK + s)*32 + lane)*4 + q2
    // t_id = cta*2 + rh ; tile row r_cta = rh*16 + rl ; W row = (r_cta>>3)*1024 + cta*8 + (r_cta&7)
    int total = 256 * NK * 128;
    __half2* dst = reinterpret_cast<__half2*>(outp);
    for (int u = tid; u < total; u += nth) {
        int q2   = u & 3;
        int lane = (u >> 2) & 31;
        int rest = u >> 7;
        int s    = rest % NK;
        int t_id = rest / NK;
        int rl = (lane >> 2) + ((q2 & 1) << 3);
        int kl = ((lane & 3) << 1) + ((q2 & 2) << 2);
        int c = t_id >> 1, rh = t_id & 1;
        int r_cta = rh * 16 + rl;
        int row = (r_cta >> 3) * 1024 + c * 8 + (r_cta & 7);
        int kg = s * 16 + kl;
        float v0, v1;
        if (kg < Ka) {
            v0 = Wa[(size_t)row * Ka + kg];
            v1 = Wa[(size_t)row * Ka + kg + 1];
        } else {
            int kk = kg - Ka;
            v0 = Wb[(size_t)row * Kb + kk];
            v1 = Wb[(size_t)row * Kb + kk + 1];
        }
        dst[u] = __floats2half2_rn(v0, v1);
    }
}

__global__ void prep_kernel(const float* __restrict__ x,
                            const float* __restrict__ Wih0, const float* __restrict__ Whh0,
                            const float* __restrict__ Wih1, const float* __restrict__ Whh1) {
    int tid = blockIdx.x * blockDim.x + threadIdx.x;
    int nth = gridDim.x * blockDim.x;
    {   // x -> fp16
        const int n2 = (Bq * Sq * Dq) / 2;
        __half2* dst = reinterpret_cast<__half2*>(g_x16);
        const float2* src = reinterpret_cast<const float2*>(x);
        for (int i = tid; i < n2; i += nth) {
            float2 v = src[i];
            dst[i] = __floats2half2_rn(v.x, v.y);
        }
    }
    pack_body(Wih0, Whh0, 512, 1024, 96, g_pack0, tid, nth);
    pack_body(Wih1, Whh1, 1024, 1024, 128, g_pack1, tid, nth);
    {   // state init
        const int n = Bq * Hq;
        const __half z = __float2half(0.0f);
        for (int i = tid; i < n; i += nth) {
            g_h0[0][i] = z; g_h0[1][i] = z;
            g_h1[0][i] = z; g_h1[1][i] = z;
            g_c0[i] = 0.0f; g_c1[i] = 0.0f;
        }
    }
    if (tid == 0) { g_bar_count = 0; g_bar_gen = 0; }
}

// ---------------- main persistent kernel ----------------
// smem (dynamic, 158976 B):
//   As  : uint4[3][1024]   A frags, 3 bufs x 16KB       @ 0
//   Zs  : half[3][64*264]  z batch-major, padded rows    @ 49152
//   gbuf: float[32][66]    gate exchange                 @ 150528
#define SMEM_BYTES 158976

__device__ __forceinline__ void grid_sync() {
    __threadfence();
    __syncthreads();
    if (threadIdx.x == 0) {
        unsigned gen = g_bar_gen;
        if (atomicAdd(&g_bar_count, 1) == NBLK - 1) {
            g_bar_count = 0;
            __threadfence();
            g_bar_gen = gen + 1;
        } else {
            while (g_bar_gen == gen) { }
        }
    }
    __syncthreads();
}

#define MMA16816(d, a, b0, b1)                                             \
    asm volatile("mma.sync.aligned.m16n8k16.row.col.f32.f16.f16.f32 "      \
                 "{%0,%1,%2,%3}, {%4,%5,%6,%7}, {%8,%9}, {%0,%1,%2,%3};\n" \
                 : "+f"(d[0]), "+f"(d[1]), "+f"(d[2]), "+f"(d[3])          \
                 : "r"(a.x), "r"(a.y), "r"(a.z), "r"(a.w), "r"(b0), "r"(b1))

__device__ __forceinline__ void cpa16(void* dst, const void* src) {
    unsigned d = (unsigned)__cvta_generic_to_shared(dst);
    asm volatile("cp.async.cg.shared.global [%0], [%1], 16;\n" :: "r"(d), "l"(src));
}

__device__ __forceinline__ float sigmf(float x) { return 1.0f / (1.0f + __expf(-x)); }
__device__ __forceinline__ float tanhfast(float x) {
    float e = __expf(2.0f * x);           // inf-safe: e=inf -> 1, e=0 -> -1
    return 1.0f - 2.0f / (e + 1.0f);
}

__device__ __forceinline__ void do_layer(int l, int t,
                                         const float* __restrict__ bi,
                                         const float* __restrict__ bh,
                                         float* __restrict__ out) {
    extern __shared__ char smem_[];
    uint4*  As   = reinterpret_cast<uint4*>(smem_);
    __half* Zs   = reinterpret_cast<__half*>(smem_ + 49152);
    float*  gbuf = reinterpret_cast<float*>(smem_ + 150528);

    const int tid = threadIdx.x;
    const int NCH = l ? 8 : 6;
    const int NK  = l ? 128 : 96;
    const __half* pb = l ? g_pack1 : g_pack0;

    float acc[4] = {0.f, 0.f, 0.f, 0.f};

    auto load_chunk = [&](int ch, int buf) {
        #pragma unroll
        for (int i = 0; i < 2; i++) {                 // A: 1024 x 16B
            int o = tid + i * 512;
            int rhh = o >> 9, rest = o & 511;
            const __half* src =
                pb + ((size_t)(blockIdx.x * 2 + rhh) * NK + ch * 16) * 256 + rest * 8;
            cpa16(As + buf * 1024 + o, src);
        }
        const __half* base; size_t rstride; size_t off;
        if (l == 0) {
            if (ch < 2) { base = g_x16; rstride = (size_t)Sq * Dq; off = (size_t)t * Dq + ch * 256; }
            else        { base = g_h0[(t + 1) & 1]; rstride = Hq; off = (size_t)(ch * 256 - 512); }
        } else {
            if (ch < 4) { base = g_h0[t & 1]; rstride = Hq; off = (size_t)(ch * 256); }
            else        { base = g_h1[(t + 1) & 1]; rstride = Hq; off = (size_t)(ch * 256 - 1024); }
        }
        #pragma unroll
        for (int i = 0; i < 4; i++) {                 // z: 64 rows x 256 halves
            int o = tid + i * 512;
            int b = o >> 5, seg = o & 31;
            cpa16(Zs + buf * 16896 + b * 264 + seg * 8,
                  base + (size_t)b * rstride + off + seg * 8);
        }
        asm volatile("cp.async.commit_group;\n" ::);
    };

    const int lane = tid & 31, w = tid >> 5;
    const int rh = w & 1, cg = w >> 1;                // 16 warps: rh 0..1, cg 0..7

    load_chunk(0, 0);
    load_chunk(1, 1);
    for (int ch = 0; ch < NCH; ++ch) {
        if (ch + 1 < NCH) asm volatile("cp.async.wait_group 1;\n" ::);
        else              asm volatile("cp.async.wait_group 0;\n" ::);
        __syncthreads();                               // one sync per chunk
        if (ch + 2 < NCH) load_chunk(ch + 2, (ch + 2) % 3);
        {
            const int buf = ch % 3;
            const uint4*  Ab = As + buf * 1024 + rh * 512 + lane;
            const __half* zb = Zs + buf * 16896 +
                               (cg * 8 + (lane >> 2)) * 264 + ((lane & 3) << 1);
            #pragma unroll
            for (int sl = 0; sl < 16; ++sl) {
                uint4 a = Ab[sl * 32];
                unsigned b0 = *reinterpret_cast<const unsigned*>(zb + sl * 16);
                unsigned b1 = *reinterpret_cast<const unsigned*>(zb + sl * 16 + 8);
                MMA16816(acc, a, b0, b1);
            }
        }
    }

    // gate exchange
    {
        int r0  = rh * 16 + (lane >> 2);
        int col = cg * 8 + ((lane & 3) << 1);
        gbuf[r0 * 66 + col]           = acc[0];
        gbuf[r0 * 66 + col + 1]       = acc[1];
        gbuf[(r0 + 8) * 66 + col]     = acc[2];
        gbuf[(r0 + 8) * 66 + col + 1] = acc[3];
    }
    __syncthreads();

    // fused LSTM cell: thread -> (b = tid>>3, hr = tid&7), coalesced stores
    float*  cst  = l ? g_c1 : g_c0;
    __half* hdst = l ? g_h1[t & 1] : g_h0[t & 1];
    {
        int b  = tid >> 3, hr = tid & 7;
        int hh = blockIdx.x * 8 + hr;
        float gi = gbuf[hr * 66 + b]        + bi[hh]        + bh[hh];
        float gf = gbuf[(8 + hr) * 66 + b]  + bi[1024 + hh] + bh[1024 + hh];
        float gg = gbuf[(16 + hr) * 66 + b] + bi[2048 + hh] + bh[2048 + hh];
        float go = gbuf[(24 + hr) * 66 + b] + bi[3072 + hh] + bh[3072 + hh];
        float cprev = cst[b * Hq + hh];
        float cn = sigmf(gf) * cprev + sigmf(gi) * tanhfast(gg);
        float hn = sigmf(go) * tanhfast(cn);
        cst[b * Hq + hh] = cn;
        hdst[(size_t)b * Hq + hh] = __float2half_rn(hn);
        if (l) {
            size_t ob = (size_t)b * Sq * Hq + (size_t)t * Hq + hh;
            out[ob] = hn;
            out[BSH + ob] = cn;
            if (t == Sq - 1) {
                out[2 * BSH + (size_t)b * Hq + hh] = hn;
                out[2 * BSH + (size_t)Bq * Hq + (size_t)b * Hq + hh] = cn;
            }
        }
    }
    __syncthreads();
}

__global__ void __launch_bounds__(512, 1)
lstm_main(const float* __restrict__ bi0, const float* __restrict__ bh0,
          const float* __restrict__ bi1, const float* __restrict__ bh1,
          float* __restrict__ out) {
    // phase p: layer0 step p + layer1 step p-1, one grid barrier per phase
    for (int p = 0; p <= Sq; ++p) {
        if (p < Sq)  do_layer(0, p,     bi0, bh0, out);
        if (p >= 1)  do_layer(1, p - 1, bi1, bh1, out);
        grid_sync();
    }
}

// ---------------- launch ----------------
extern "C" void kernel_launch(void* const* d_in, const int* in_sizes, int n_in,
                              void* d_out, int out_size) {
    (void)in_sizes; (void)n_in; (void)out_size;
    const float* x    = (const float*)d_in[0];
    const float* Wih0 = (const float*)d_in[1];
    const float* Whh0 = (const float*)d_in[2];
    const float* bih0 = (const float*)d_in[3];
    const float* bhh0 = (const float*)d_in[4];
    const float* Wih1 = (const float*)d_in[5];
    const float* Whh1 = (const float*)d_in[6];
    const float* bih1 = (const float*)d_in[7];
    const float* bhh1 = (const float*)d_in[8];
    float* out = (float*)d_out;

    prep_kernel<<<2048, 256>>>(x, Wih0, Whh0, Wih1, Whh1);

    cudaFuncSetAttribute(lstm_main, cudaFuncAttributeMaxDynamicSharedMemorySize, SMEM_BYTES);
    lstm_main<<<NBLK, 512, SMEM_BYTES>>>(bih0, bhh0, bih1, bhh1, out);
}

// round 8
// speedup vs baseline: 2.6751x; 2.6751x over previous
#include <cuda_runtime.h>
#include <cuda_fp16.h>
#include <cstdint>
#include <cstddef>

#define Bq 64
#define Sq 1024
#define Dq 512
#define Hq 1024
#define NBLK 128
#define BSH ((size_t)Bq * Sq * Hq)

// ---------------- persistent device state ----------------
// A fragment-packed weights (16B per (tile,slice,lane))
__device__ uint4 g_pack0u[(size_t)4096 * 1536 / 8];   // 12.6 MB
__device__ uint4 g_pack1u[(size_t)4096 * 2048 / 8];   // 16.8 MB
// B fragment-packed activations: uint4 idx = s*128 + ch2*64 + khalf*32 + lane
// u32[cg] = z[col = ch2*32+cg*8+(lane>>2)][k = s*16+khalf*8+(lane&3)*2 .. +1]
__device__ uint4 g_zx[(size_t)1024 * 4096];           // 67 MB: all x, pre-packed per t
__device__ uint4 g_zh0[2][8192];                      // h0 (1024 feat), parity buffered
__device__ uint4 g_zh1[2][8192];                      // h1
__device__ float g_c0[Bq * Hq];                       // c state, [b][h]
__device__ float g_c1[Bq * Hq];
__device__ float g_bias0[4096];                       // bi+bh combined
__device__ float g_bias1[4096];
__device__ unsigned g_bar_count;
__device__ volatile unsigned g_bar_gen;

// ---------------- prep ----------------
__device__ __forceinline__ void pack_body(const float* __restrict__ Wa,
                                          const float* __restrict__ Wb,
                                          int Ka, int Kb, int NK, __half2* dst,
                                          int tid, int nth) {
    // half2 u = ((t_id*NK + s)*32 + lane)*4 + q2 ; t_id = cta*2 + rh
    // r_cta = rh*16 + rl ; W row = (r_cta>>3)*1024 + cta*8 + (r_cta&7)
    int total = 256 * NK * 128;
    for (int u = tid; u < total; u += nth) {
        int q2   = u & 3;
        int lane = (u >> 2) & 31;
        int rest = u >> 7;
        int s    = rest % NK;
        int t_id = rest / NK;
        int rl = (lane >> 2) + ((q2 & 1) << 3);
        int kl = ((lane & 3) << 1) + ((q2 & 2) << 2);
        int c = t_id >> 1, rh = t_id & 1;
        int r_cta = rh * 16 + rl;
        int row = (r_cta >> 3) * 1024 + c * 8 + (r_cta & 7);
        int kg = s * 16 + kl;
        float v0, v1;
        if (kg < Ka) {
            v0 = Wa[(size_t)row * Ka + kg];
            v1 = Wa[(size_t)row * Ka + kg + 1];
        } else {
            int kk = kg - Ka;
            v0 = Wb[(size_t)row * Kb + kk];
            v1 = Wb[(size_t)row * Kb + kk + 1];
        }
        dst[u] = __floats2half2_rn(v0, v1);
    }
}

__global__ void prep_kernel(const float* __restrict__ x,
                            const float* __restrict__ Wih0, const float* __restrict__ Whh0,
                            const float* __restrict__ bih0, const float* __restrict__ bhh0,
                            const float* __restrict__ Wih1, const float* __restrict__ Whh1,
                            const float* __restrict__ bih1, const float* __restrict__ bhh1) {
    int tid = blockIdx.x * blockDim.x + threadIdx.x;
    int nth = gridDim.x * blockDim.x;

    // x -> B-fragment-packed g_zx
    {
        __half2* dst = reinterpret_cast<__half2*>(g_zx);
        const long total = (long)1024 * 16384;   // half2 units
        for (long u = tid; u < total; u += nth) {
            int cg    = (int)(u & 3);
            int lane  = (int)((u >> 2) & 31);
            int khalf = (int)((u >> 7) & 1);
            int ch2   = (int)((u >> 8) & 1);
            int s     = (int)((u >> 9) & 31);
            int t     = (int)(u >> 14);
            int b = ch2 * 32 + cg * 8 + (lane >> 2);
            int k = s * 16 + khalf * 8 + ((lane & 3) << 1);
            const float2 v = *reinterpret_cast<const float2*>(
                x + ((size_t)b * Sq + t) * Dq + k);
            dst[u] = __floats2half2_rn(v.x, v.y);
        }
    }
    pack_body(Wih0, Whh0, 512, 1024, 96, reinterpret_cast<__half2*>(g_pack0u), tid, nth);
    pack_body(Wih1, Whh1, 1024, 1024, 128, reinterpret_cast<__half2*>(g_pack1u), tid, nth);
    // bias combine + state init
    for (int i = tid; i < 4096; i += nth) {
        g_bias0[i] = bih0[i] + bhh0[i];
        g_bias1[i] = bih1[i] + bhh1[i];
    }
    {
        uint4 z4 = make_uint4(0, 0, 0, 0);
        for (int i = tid; i < 8192; i += nth) {
            g_zh0[1][i] = z4; g_zh1[1][i] = z4;
        }
        for (int i = tid; i < Bq * Hq; i += nth) { g_c0[i] = 0.0f; g_c1[i] = 0.0f; }
    }
    if (tid == 0) { g_bar_count = 0; g_bar_gen = 0; }
}

// ---------------- main persistent kernel ----------------
#define SMEM_BYTES 32768   // gbuf: 16 warps x 32 lanes x 16 floats

__device__ __forceinline__ void grid_sync() {
    __threadfence();
    __syncthreads();
    if (threadIdx.x == 0) {
        unsigned gen = g_bar_gen;
        if (atomicAdd(&g_bar_count, 1) == NBLK - 1) {
            g_bar_count = 0;
            __threadfence();
            g_bar_gen = gen + 1;
        } else {
            while (g_bar_gen == gen) { }
        }
    }
    __syncthreads();
}

#define MMA16816(d, a, b0, b1)                                             \
    asm volatile("mma.sync.aligned.m16n8k16.row.col.f32.f16.f16.f32 "      \
                 "{%0,%1,%2,%3}, {%4,%5,%6,%7}, {%8,%9}, {%0,%1,%2,%3};\n" \
                 : "+f"((d)[0]), "+f"((d)[1]), "+f"((d)[2]), "+f"((d)[3])  \
                 : "r"((a).x), "r"((a).y), "r"((a).z), "r"((a).w),         \
                   "r"(b0), "r"(b1))

__device__ __forceinline__ float sigmf(float x) { return 1.0f / (1.0f + __expf(-x)); }
__device__ __forceinline__ float tanhfast(float x) {
    float e = __expf(2.0f * x);            // inf-safe
    return 1.0f - 2.0f / (e + 1.0f);
}

__device__ __forceinline__ void do_layer(int l, int t,
                                         const float* __restrict__ bias,
                                         float* __restrict__ out) {
    extern __shared__ float gbuf[];        // [w][lane][mma][reg] = 8192 floats
    const int tid = threadIdx.x, lane = tid & 31, w = tid >> 5;
    const int spl = w & 3, ch2 = (w >> 2) & 1, rh = w >> 3;   // 4 x 2 x 2
    const int cta = blockIdx.x;
    const int NCH = l ? 8 : 6, NK = l ? 128 : 96;
    const uint4* __restrict__ Ap =
        (l ? g_pack1u : g_pack0u) + ((size_t)(cta * 2 + rh) * NK) * 32 + lane;

    const int pcur = t & 1, pprev = (t + 1) & 1;

    float acc[16];
#pragma unroll
    for (int i = 0; i < 16; i++) acc[i] = 0.f;

    for (int ch = 0; ch < NCH; ++ch) {
        const uint4* __restrict__ Bp;
        if (l == 0) {
            if (ch < 2) Bp = g_zx + (size_t)t * 4096 + ch * 2048;
            else        Bp = g_zh0[pprev] + (ch - 2) * 2048;
        } else {
            if (ch < 4) Bp = g_zh0[pcur] + ch * 2048;
            else        Bp = g_zh1[pprev] + (ch - 4) * 2048;
        }
        Bp += ch2 * 64 + lane;
        const uint4* __restrict__ Ac = Ap + (size_t)(ch * 16) * 32;
#pragma unroll
        for (int j = 0; j < 4; j++) {
            const int sl = spl + j * 4;
            uint4 a  = Ac[sl * 32];
            uint4 bl = Bp[sl * 128];        // khalf 0: b0 for 4 col-groups
            uint4 bh = Bp[sl * 128 + 32];   // khalf 1: b1 for 4 col-groups
            MMA16816(acc +  0, a, bl.x, bh.x);
            MMA16816(acc +  4, a, bl.y, bh.y);
            MMA16816(acc +  8, a, bl.z, bh.z);
            MMA16816(acc + 12, a, bl.w, bh.w);
        }
    }

    // stash partials (per-warp region, no conflicts)
    float* gw = gbuf + (w * 32 + lane) * 16;
#pragma unroll
    for (int i = 0; i < 16; i++) gw[i] = acc[i];
    __syncthreads();

    // fused LSTM cell: thread -> (b = tid>>3, hp = tid&7)
    {
        const int b = tid >> 3, hp = tid & 7;
        const int hh = cta * 8 + hp;
        const int ch2e = b >> 5, b32 = b & 31, mma = b32 >> 3, n8 = b32 & 7;
        float g4[4];
#pragma unroll
        for (int q = 0; q < 4; q++) {
            int rt  = q * 8 + hp;               // row within 32-row CTA tile
            int rhe = rt >> 4, h16 = rt & 15;
            int L   = ((h16 & 7) << 2) | (n8 >> 1);
            int reg = (n8 & 1) + ((h16 >> 3) << 1);
            int base = ((rhe * 8 + ch2e * 4) * 32 + L) * 16 + mma * 4 + reg;
            g4[q] = gbuf[base] + gbuf[base + 512] + gbuf[base + 1024] +
                    gbuf[base + 1536] + bias[q * 1024 + hh];
        }
        float* cst = l ? g_c1 : g_c0;
        float cprev = cst[b * Hq + hh];
        float cn = sigmf(g4[1]) * cprev + sigmf(g4[0]) * tanhfast(g4[2]);
        float hn = sigmf(g4[3]) * tanhfast(cn);
        cst[b * Hq + hh] = cn;
        // scatter h into B-fragment-packed state
        {
            __half* zh = reinterpret_cast<__half*>(l ? g_zh1[pcur] : g_zh0[pcur]);
            int sf = hh >> 4, kh = (hh >> 3) & 1;
            int lz = ((b & 7) << 2) | ((hh >> 1) & 3);
            int cg = (b >> 3) & 3;
            zh[(size_t)(((sf * 2 + ch2e) * 2 + kh) * 32 + lz) * 8 + cg * 2 + (hh & 1)] =
                __float2half_rn(hn);
        }
        if (l) {
            size_t ob = (size_t)b * Sq * Hq + (size_t)t * Hq + hh;
            out[ob] = hn;
            out[BSH + ob] = cn;
            if (t == Sq - 1) {
                out[2 * BSH + (size_t)b * Hq + hh] = hn;
                out[2 * BSH + (size_t)Bq * Hq + (size_t)b * Hq + hh] = cn;
            }
        }
    }
    __syncthreads();
}

__global__ void __launch_bounds__(512, 1)
lstm_main(float* __restrict__ out) {
    // phase p: layer0 step p + layer1 step p-1, one grid barrier per phase
    for (int p = 0; p <= Sq; ++p) {
        if (p < Sq)  do_layer(0, p,     g_bias0, out);
        if (p >= 1)  do_layer(1, p - 1, g_bias1, out);
        grid_sync();
    }
}

// ---------------- launch ----------------
extern "C" void kernel_launch(void* const* d_in, const int* in_sizes, int n_in,
                              void* d_out, int out_size) {
    (void)in_sizes; (void)n_in; (void)out_size;
    const float* x    = (const float*)d_in[0];
    const float* Wih0 = (const float*)d_in[1];
    const float* Whh0 = (const float*)d_in[2];
    const float* bih0 = (const float*)d_in[3];
    const float* bhh0 = (const float*)d_in[4];
    const float* Wih1 = (const float*)d_in[5];
    const float* Whh1 = (const float*)d_in[6];
    const float* bih1 = (const float*)d_in[7];
    const float* bhh1 = (const float*)d_in[8];
    float* out = (float*)d_out;

    prep_kernel<<<4096, 256>>>(x, Wih0, Whh0, bih0, bhh0, Wih1, Whh1, bih1, bhh1);

    cudaFuncSetAttribute(lstm_main, cudaFuncAttributeMaxDynamicSharedMemorySize, SMEM_BYTES);
    lstm_main<<<NBLK, 512, SMEM_BYTES>>>(out);
}

// round 9
// speedup vs baseline: 3.0509x; 1.1405x over previous
#include <cuda_runtime.h>
#include <cuda_fp16.h>
#include <cstdint>
#include <cstddef>

#define Bq 64
#define Sq 1024
#define Dq 512
#define Hq 1024
#define NBLK 128
#define BSH ((size_t)Bq * Sq * Hq)

// ---------------- persistent device state ----------------
__device__ uint4 g_pack0u[(size_t)4096 * 1536 / 8];   // A fragment-packed weights L0
__device__ uint4 g_pack1u[(size_t)4096 * 2048 / 8];   // A fragment-packed weights L1
// B fragment-packed activations: uint4 idx = s*128 + ch2*64 + khalf*32 + lane
// u32[cg] = z[col = ch2*32+cg*8+(lane>>2)][k = s*16+khalf*8+(lane&3)*2 .. +1]
__device__ uint4 g_zx[(size_t)1024 * 4096];           // all x, pre-packed per t
__device__ uint4 g_zh0[2][8192];                      // h0, parity buffered
__device__ uint4 g_zh1[2][8192];                      // h1
__device__ float g_c0[Bq * Hq];                       // c state, [b][h]
__device__ float g_c1[Bq * Hq];
__device__ float g_bias0[4096];                       // bi+bh combined
__device__ float g_bias1[4096];
__device__ unsigned g_arrive[NBLK * 32];              // per-CTA arrive flags, 128B apart
__device__ unsigned g_gen2;                           // generation broadcast

// ---------------- prep ----------------
__device__ __forceinline__ void pack_body(const float* __restrict__ Wa,
                                          const float* __restrict__ Wb,
                                          int Ka, int Kb, int NK, __half2* dst,
                                          int tid, int nth) {
    int total = 256 * NK * 128;
    for (int u = tid; u < total; u += nth) {
        int q2   = u & 3;
        int lane = (u >> 2) & 31;
        int rest = u >> 7;
        int s    = rest % NK;
        int t_id = rest / NK;
        int rl = (lane >> 2) + ((q2 & 1) << 3);
        int kl = ((lane & 3) << 1) + ((q2 & 2) << 2);
        int c = t_id >> 1, rh = t_id & 1;
        int r_cta = rh * 16 + rl;
        int row = (r_cta >> 3) * 1024 + c * 8 + (r_cta & 7);
        int kg = s * 16 + kl;
        float v0, v1;
        if (kg < Ka) {
            v0 = Wa[(size_t)row * Ka + kg];
            v1 = Wa[(size_t)row * Ka + kg + 1];
        } else {
            int kk = kg - Ka;
            v0 = Wb[(size_t)row * Kb + kk];
            v1 = Wb[(size_t)row * Kb + kk + 1];
        }
        dst[u] = __floats2half2_rn(v0, v1);
    }
}

__global__ void prep_kernel(const float* __restrict__ x,
                            const float* __restrict__ Wih0, const float* __restrict__ Whh0,
                            const float* __restrict__ bih0, const float* __restrict__ bhh0,
                            const float* __restrict__ Wih1, const float* __restrict__ Whh1,
                            const float* __restrict__ bih1, const float* __restrict__ bhh1) {
    int tid = blockIdx.x * blockDim.x + threadIdx.x;
    int nth = gridDim.x * blockDim.x;

    {   // x -> B-fragment-packed g_zx
        __half2* dst = reinterpret_cast<__half2*>(g_zx);
        const long total = (long)1024 * 16384;
        for (long u = tid; u < total; u += nth) {
            int cg    = (int)(u & 3);
            int lane  = (int)((u >> 2) & 31);
            int khalf = (int)((u >> 7) & 1);
            int ch2   = (int)((u >> 8) & 1);
            int s     = (int)((u >> 9) & 31);
            int t     = (int)(u >> 14);
            int b = ch2 * 32 + cg * 8 + (lane >> 2);
            int k = s * 16 + khalf * 8 + ((lane & 3) << 1);
            const float2 v = *reinterpret_cast<const float2*>(
                x + ((size_t)b * Sq + t) * Dq + k);
            dst[u] = __floats2half2_rn(v.x, v.y);
        }
    }
    pack_body(Wih0, Whh0, 512, 1024, 96, reinterpret_cast<__half2*>(g_pack0u), tid, nth);
    pack_body(Wih1, Whh1, 1024, 1024, 128, reinterpret_cast<__half2*>(g_pack1u), tid, nth);
    for (int i = tid; i < 4096; i += nth) {
        g_bias0[i] = bih0[i] + bhh0[i];
        g_bias1[i] = bih1[i] + bhh1[i];
    }
    {
        uint4 z4 = make_uint4(0, 0, 0, 0);
        for (int i = tid; i < 8192; i += nth) {
            g_zh0[1][i] = z4; g_zh1[1][i] = z4;
        }
        for (int i = tid; i < Bq * Hq; i += nth) { g_c0[i] = 0.0f; g_c1[i] = 0.0f; }
        for (int i = tid; i < NBLK * 32; i += nth) g_arrive[i] = 0u;
    }
    if (tid == 0) g_gen2 = 0u;
}

// ---------------- main persistent kernel ----------------
// gbuf: 16 warps x 32 lanes x 33 floats (pad) = 67584 B
#define PSTRIDE 33
#define SMEM_BYTES (16 * 32 * PSTRIDE * 4)

__device__ __forceinline__ void grid_sync(unsigned target) {
    __syncthreads();
    __threadfence();
    const int tid = threadIdx.x;
    if (blockIdx.x == 0) {
        if (tid >= 1 && tid < NBLK) {
            unsigned v;
            do {
                asm volatile("ld.global.acquire.gpu.u32 %0, [%1];"
                             : "=r"(v) : "l"(g_arrive + tid * 32));
            } while (v < target);
        }
        __syncthreads();
        if (tid == 0)
            asm volatile("st.global.release.gpu.u32 [%0], %1;"
                         :: "l"(&g_gen2), "r"(target));
    } else {
        if (tid == 0) {
            asm volatile("st.global.release.gpu.u32 [%0], %1;"
                         :: "l"(g_arrive + blockIdx.x * 32), "r"(target));
            unsigned v;
            do {
                asm volatile("ld.global.acquire.gpu.u32 %0, [%1];"
                             : "=r"(v) : "l"(&g_gen2));
            } while (v < target);
        }
    }
    __syncthreads();
}

#define MMA16816(d, a, b0, b1)                                             \
    asm volatile("mma.sync.aligned.m16n8k16.row.col.f32.f16.f16.f32 "      \
                 "{%0,%1,%2,%3}, {%4,%5,%6,%7}, {%8,%9}, {%0,%1,%2,%3};\n" \
                 : "+f"((d)[0]), "+f"((d)[1]), "+f"((d)[2]), "+f"((d)[3])  \
                 : "r"((a).x), "r"((a).y), "r"((a).z), "r"((a).w),         \
                   "r"(b0), "r"(b1))

__device__ __forceinline__ float sigmf(float x) { return 1.0f / (1.0f + __expf(-x)); }
__device__ __forceinline__ float tanhfast(float x) {
    float e = __expf(2.0f * x);            // inf-safe
    return 1.0f - 2.0f / (e + 1.0f);
}

__device__ __forceinline__ void do_layer(int l, int t,
                                         const float* __restrict__ bias,
                                         float* __restrict__ out) {
    extern __shared__ float gbuf[];
    const int tid = threadIdx.x, lane = tid & 31, w = tid >> 5;
    const int ch2 = w & 1, spl = w >> 1;              // 2 x 8
    const int cta = blockIdx.x;
    const int NCH = l ? 8 : 6, NK = l ? 128 : 96;
    // A base for this CTA (rh0 tile); rh1 tile is +NK*32 uint4s
    const uint4* __restrict__ Abase =
        (l ? g_pack1u : g_pack0u) + ((size_t)(cta * 2) * NK) * 32 + lane;
    const int astride = NK * 32;

    const int pcur = t & 1, pprev = (t + 1) & 1;

    float acc[32];
#pragma unroll
    for (int i = 0; i < 32; i++) acc[i] = 0.f;

    for (int ch = 0; ch < NCH; ++ch) {
        const uint4* __restrict__ Bp;
        if (l == 0) {
            if (ch < 2) Bp = g_zx + (size_t)t * 4096 + ch * 2048;
            else        Bp = g_zh0[pprev] + (ch - 2) * 2048;
        } else {
            if (ch < 4) Bp = g_zh0[pcur] + ch * 2048;
            else        Bp = g_zh1[pprev] + (ch - 4) * 2048;
        }
        Bp += ch2 * 64 + lane;
        const uint4* __restrict__ Ac = Abase + (ch * 16) * 32;
#pragma unroll
        for (int j = 0; j < 2; j++) {
            const int sl = spl + j * 8;
            uint4 a0 = __ldg(Ac + sl * 32);
            uint4 a1 = __ldg(Ac + sl * 32 + astride);
            uint4 bl = __ldcg(Bp + sl * 128);         // khalf 0 -> b0
            uint4 bh = __ldcg(Bp + sl * 128 + 32);    // khalf 1 -> b1
            MMA16816(acc +  0, a0, bl.x, bh.x);       // tile (rh, cg) = rh*4+cg
            MMA16816(acc +  4, a0, bl.y, bh.y);
            MMA16816(acc +  8, a0, bl.z, bh.z);
            MMA16816(acc + 12, a0, bl.w, bh.w);
            MMA16816(acc + 16, a1, bl.x, bh.x);
            MMA16816(acc + 20, a1, bl.y, bh.y);
            MMA16816(acc + 24, a1, bl.z, bh.z);
            MMA16816(acc + 28, a1, bl.w, bh.w);
        }
    }

    // stash partials (padded stride -> conflict-free writes)
    float* gw = gbuf + (w * 32 + lane) * PSTRIDE;
#pragma unroll
    for (int i = 0; i < 32; i++) gw[i] = acc[i];
    __syncthreads();

    // fused LSTM cell: thread -> (b = tid>>3, hp = tid&7)
    {
        const int b = tid >> 3, hp = tid & 7;
        const int hh = cta * 8 + hp;
        const int ch2e = b >> 5, b32 = b & 31, cg = b32 >> 3, coln = b32 & 7;
        float g4[4];
#pragma unroll
        for (int q = 0; q < 4; q++) {
            int rt  = q * 8 + hp;
            int rhe = rt >> 4, h16 = rt & 15;
            int L   = ((h16 & 7) << 2) | (coln >> 1);
            int r   = (coln & 1) + ((h16 >> 3) << 1);
            int tile = rhe * 4 + cg;
            int base = (ch2e * 32 + L) * PSTRIDE + tile * 4 + r;
            float s = bias[q * 1024 + hh];
#pragma unroll
            for (int sp = 0; sp < 8; sp++)
                s += gbuf[base + sp * (2 * 32 * PSTRIDE)];
            g4[q] = s;
        }
        float* cst = l ? g_c1 : g_c0;
        float cprev = cst[b * Hq + hh];
        float cn = sigmf(g4[1]) * cprev + sigmf(g4[0]) * tanhfast(g4[2]);
        float hn = sigmf(g4[3]) * tanhfast(cn);
        cst[b * Hq + hh] = cn;
        // scatter h into B-fragment-packed state
        {
            __half* zh = reinterpret_cast<__half*>(l ? g_zh1[pcur] : g_zh0[pcur]);
            int sf = hh >> 4, kh = (hh >> 3) & 1;
            int lz = ((b & 7) << 2) | ((hh >> 1) & 3);
            int cgz = (b >> 3) & 3;
            zh[(size_t)(((sf * 2 + ch2e) * 2 + kh) * 32 + lz) * 8 + cgz * 2 + (hh & 1)] =
                __float2half_rn(hn);
        }
        if (l) {
            size_t ob = (size_t)b * Sq * Hq + (size_t)t * Hq + hh;
            out[ob] = hn;
            out[BSH + ob] = cn;
            if (t == Sq - 1) {
                out[2 * BSH + (size_t)b * Hq + hh] = hn;
                out[2 * BSH + (size_t)Bq * Hq + (size_t)b * Hq + hh] = cn;
            }
        }
    }
    __syncthreads();
}

__global__ void __launch_bounds__(512, 1)
lstm_main(float* __restrict__ out) {
    // phase p: layer0 step p + layer1 step p-1, one grid barrier per phase
    for (int p = 0; p <= Sq; ++p) {
        if (p < Sq)  do_layer(0, p,     g_bias0, out);
        if (p >= 1)  do_layer(1, p - 1, g_bias1, out);
        grid_sync((unsigned)(p + 1));
    }
}

// ---------------- launch ----------------
extern "C" void kernel_launch(void* const* d_in, const int* in_sizes, int n_in,
                              void* d_out, int out_size) {
    (void)in_sizes; (void)n_in; (void)out_size;
    const float* x    = (const float*)d_in[0];
    const float* Wih0 = (const float*)d_in[1];
    const float* Whh0 = (const float*)d_in[2];
    const float* bih0 = (const float*)d_in[3];
    const float* bhh0 = (const float*)d_in[4];
    const float* Wih1 = (const float*)d_in[5];
    const float* Whh1 = (const float*)d_in[6];
    const float* bih1 = (const float*)d_in[7];
    const float* bhh1 = (const float*)d_in[8];
    float* out = (float*)d_out;

    prep_kernel<<<4096, 256>>>(x, Wih0, Whh0, bih0, bhh0, Wih1, Whh1, bih1, bhh1);

    cudaFuncSetAttribute(lstm_main, cudaFuncAttributeMaxDynamicSharedMemorySize, SMEM_BYTES);
    lstm_main<<<NBLK, 512, SMEM_BYTES>>>(out);
}